// round 5
// baseline (speedup 1.0000x reference)
#include <cuda_runtime.h>

// TemporalTransformerBlock on GB300 — R4.
//  - All weights pre-duplicated to (w,w) 64-bit pairs in __constant__ memory:
//    lane-uniform LDCU on the uniform-const port (floor=1), zero L1tex traffic,
//    no per-use mov.b64 dup. Filled by a prep kernel + cudaMemcpyToSymbolAsync.
//  - Layer 1 collapsed algebraically: input proj is rank-1, so layer-1 QKV are
//    affine in scalar x  =>  logits = a*x_t*x_s + b*x_t + g*x_s + d per head,
//    ctx_h = Xbar_h * av + cv. Attention+Wo become ~290 fma2 instead of ~2100,
//    and the layer-1 K/V smem tile disappears.
//  - Layer 2 full, f32x2-packed (two sequences per lane), KV tile in smem.

#define NSEQ   65536
#define SEQ_T  24
#define DM     16
#define NH     4
#define HDIM   4
#define DFF_   64
#define NL     2
#define WPC    4
#define CTA_THREADS (WPC * 32)

typedef unsigned long long f2;   // packed (seqA, seqB) fp32 pair

__device__ __forceinline__ f2 pk(float x, float y) {
    f2 r; asm("mov.b64 %0, {%1, %2};" : "=l"(r) : "f"(x), "f"(y)); return r;
}
__device__ __forceinline__ f2 dupf(float x) {
    f2 r; asm("mov.b64 %0, {%1, %1};" : "=l"(r) : "f"(x)); return r;
}
__device__ __forceinline__ void upk(f2 v, float& x, float& y) {
    asm("mov.b64 {%0, %1}, %2;" : "=f"(x), "=f"(y) : "l"(v));
}
__device__ __forceinline__ f2 fma2(f2 a, f2 b, f2 c) {
    f2 d; asm("fma.rn.f32x2 %0, %1, %2, %3;" : "=l"(d) : "l"(a), "l"(b), "l"(c)); return d;
}
__device__ __forceinline__ f2 add2(f2 a, f2 b) {
    f2 d; asm("add.rn.f32x2 %0, %1, %2;" : "=l"(d) : "l"(a), "l"(b)); return d;
}
__device__ __forceinline__ f2 mul2(f2 a, f2 b) {
    f2 d; asm("mul.rn.f32x2 %0, %1, %2;" : "=l"(d) : "l"(a), "l"(b)); return d;
}
__device__ __forceinline__ float ex2(float x) {
    float r; asm("ex2.approx.f32 %0, %1;" : "=f"(r) : "f"(x)); return r;
}
__device__ __forceinline__ float rcpf(float x) {
    float r; asm("rcp.approx.f32 %0, %1;" : "=f"(r) : "f"(x)); return r;
}

// All weights, pre-duplicated as (w,w) 64-bit pairs.
struct CW {
    f2 Wqkv2[3*DM][DM];          // layer-2 QKV
    f2 bqkv2[3*DM];
    f2 Wo2[DM][DM];              // layer-2 output proj
    f2 bo2[DM];
    f2 W1[NL][DFF_][DM];
    f2 b1[NL][DFF_];
    f2 W2T[NL][DFF_][DM];        // transposed [j][d]
    f2 b2[NL][DM];
    f2 ln1w[NL][DM], ln1b[NL][DM], ln2w[NL][DM], ln2b[NL][DM];
    f2 Win[DM], bin_[DM], Wout[DM], bout_;
    // layer-1 collapsed-attention coefficients (include 0.5*log2e scale)
    f2 A1[NH], B1[NH], G1[NH], D1[NH];
    f2 MoT[DM][NH];              // Mo transposed: [d][h]
    f2 co[DM];
};

__device__ CW g_stage;
__constant__ CW cw;

// ---------------- prep kernel: pack + duplicate + layer-1 collapse ----------
__global__ void prep_kernel(
    const float* __restrict__ Wqkv, const float* __restrict__ bqkv,
    const float* __restrict__ Wo,   const float* __restrict__ bo,
    const float* __restrict__ W1,   const float* __restrict__ b1,
    const float* __restrict__ W2,   const float* __restrict__ b2,
    const float* __restrict__ ln1w, const float* __restrict__ ln1b,
    const float* __restrict__ ln2w, const float* __restrict__ ln2b,
    const float* __restrict__ Win,  const float* __restrict__ bin_,
    const float* __restrict__ Wout, const float* __restrict__ bout_)
{
    const int gtid = blockIdx.x * blockDim.x + threadIdx.x;
    const int gstride = gridDim.x * blockDim.x;

    for (int i = gtid; i < 3*DM*DM; i += gstride) (&g_stage.Wqkv2[0][0])[i] = dupf(Wqkv[3*DM*DM + i]);
    for (int i = gtid; i < 3*DM;    i += gstride) g_stage.bqkv2[i] = dupf(bqkv[3*DM + i]);
    for (int i = gtid; i < DM*DM;   i += gstride) (&g_stage.Wo2[0][0])[i] = dupf(Wo[DM*DM + i]);
    for (int i = gtid; i < DM;      i += gstride) g_stage.bo2[i] = dupf(bo[DM + i]);
    for (int i = gtid; i < NL*DFF_*DM; i += gstride) (&g_stage.W1[0][0][0])[i] = dupf(W1[i]);
    for (int i = gtid; i < NL*DFF_;    i += gstride) (&g_stage.b1[0][0])[i]    = dupf(b1[i]);
    for (int i = gtid; i < NL*DFF_*DM; i += gstride) {
        int l = i / (DFF_*DM), r = i % (DFF_*DM);
        int j = r / DM, d = r % DM;
        g_stage.W2T[l][j][d] = dupf(W2[l*DM*DFF_ + d*DFF_ + j]);
    }
    for (int i = gtid; i < NL*DM; i += gstride) {
        (&g_stage.b2[0][0])[i]   = dupf(b2[i]);
        (&g_stage.ln1w[0][0])[i] = dupf(ln1w[i]);
        (&g_stage.ln1b[0][0])[i] = dupf(ln1b[i]);
        (&g_stage.ln2w[0][0])[i] = dupf(ln2w[i]);
        (&g_stage.ln2b[0][0])[i] = dupf(ln2b[i]);
    }
    for (int i = gtid; i < DM; i += gstride) {
        g_stage.Win[i]  = dupf(Win[i]);
        g_stage.bin_[i] = dupf(bin_[i]);
        g_stage.Wout[i] = dupf(Wout[i]);
    }
    if (gtid == 0) g_stage.bout_ = dupf(bout_[0]);

    // layer-1 collapse coefficients (block 0 only)
    __shared__ float aux_a[3*DM], aux_c[3*DM];
    if (blockIdx.x == 0) {
        const int tid = threadIdx.x;
        if (tid < 3*DM) {
            float a = 0.f, c = 0.f;
            for (int d = 0; d < DM; d++) {
                float w = Wqkv[tid*DM + d];          // layer 0
                a += w * Win[d];
                c += w * bin_[d];
            }
            aux_a[tid] = a;
            aux_c[tid] = c + bqkv[tid];
        }
        __syncthreads();
        const float cs = 0.5f * 1.4426950408889634f;   // scale * log2(e)
        if (tid < NH) {
            float al = 0.f, be = 0.f, ga = 0.f, de = 0.f;
            for (int e = 0; e < HDIM; e++) {
                float aq = aux_a[tid*HDIM + e],      cq = aux_c[tid*HDIM + e];
                float ak = aux_a[DM + tid*HDIM + e], ck = aux_c[DM + tid*HDIM + e];
                al += aq*ak; be += aq*ck; ga += cq*ak; de += cq*ck;
            }
            g_stage.A1[tid] = dupf(cs*al);
            g_stage.B1[tid] = dupf(cs*be);
            g_stage.G1[tid] = dupf(cs*ga);
            g_stage.D1[tid] = dupf(cs*de);
        }
        if (tid >= 32 && tid < 32 + NH*DM) {
            int idx = tid - 32, h = idx >> 4, d = idx & 15;
            float m = 0.f;
            for (int e = 0; e < HDIM; e++)
                m += aux_a[2*DM + h*HDIM + e] * Wo[d*DM + h*HDIM + e];   // layer 0 Wo
            g_stage.MoT[d][h] = dupf(m);
        }
        if (tid >= 96 && tid < 96 + DM) {
            int d = tid - 96;
            float c = bo[d];
            for (int e = 0; e < DM; e++)
                c += aux_c[2*DM + e] * Wo[d*DM + e];
            g_stage.co[d] = dupf(c);
        }
    }
}

// ---------------- main-kernel helpers ---------------------------------------
__device__ __forceinline__ f2 dot16c(const f2* h, const f2* w, f2 init) {
    f2 s0 = fma2(h[0],  w[0],  init);
    f2 s1 = mul2(h[1],  w[1]);
    s0 = fma2(h[2],  w[2],  s0);  s1 = fma2(h[3],  w[3],  s1);
    s0 = fma2(h[4],  w[4],  s0);  s1 = fma2(h[5],  w[5],  s1);
    s0 = fma2(h[6],  w[6],  s0);  s1 = fma2(h[7],  w[7],  s1);
    s0 = fma2(h[8],  w[8],  s0);  s1 = fma2(h[9],  w[9],  s1);
    s0 = fma2(h[10], w[10], s0);  s1 = fma2(h[11], w[11], s1);
    s0 = fma2(h[12], w[12], s0);  s1 = fma2(h[13], w[13], s1);
    s0 = fma2(h[14], w[14], s0);  s1 = fma2(h[15], w[15], s1);
    return add2(s0, s1);
}

__device__ __forceinline__ void lnorm2(f2* h, const f2* w, const f2* b) {
    f2 s0 = add2(h[0], h[1]), s1 = add2(h[2], h[3]);
    f2 s2 = add2(h[4], h[5]), s3 = add2(h[6], h[7]);
    s0 = add2(s0, add2(h[8],  h[9]));
    s1 = add2(s1, add2(h[10], h[11]));
    s2 = add2(s2, add2(h[12], h[13]));
    s3 = add2(s3, add2(h[14], h[15]));
    f2 sum = add2(add2(s0, s1), add2(s2, s3));
    f2 nmu = mul2(sum, dupf(-1.0f / DM));
    f2 v0 = 0ull, v1 = 0ull;
#pragma unroll
    for (int d = 0; d < DM; d += 2) {
        f2 c0 = add2(h[d],   nmu);
        f2 c1 = add2(h[d+1], nmu);
        v0 = fma2(c0, c0, v0);
        v1 = fma2(c1, c1, v1);
    }
    f2 var = add2(v0, v1);
    float va, vb; upk(var, va, vb);
    va = rsqrtf(va * (1.0f / DM) + 1e-5f);
    vb = rsqrtf(vb * (1.0f / DM) + 1e-5f);
    f2 inv = pk(va, vb);
#pragma unroll
    for (int d = 0; d < DM; d++) {
        f2 c = add2(h[d], nmu);
        h[d] = fma2(mul2(c, inv), w[d], b[d]);
    }
}

__device__ __forceinline__ void ffn(f2* h, int l) {
    f2 acc[DM];
#pragma unroll
    for (int d = 0; d < DM; d++) acc[d] = cw.b2[l][d];
#pragma unroll 4
    for (int j = 0; j < DFF_; j++) {
        f2 a = dot16c(h, cw.W1[l][j], cw.b1[l][j]);
        float aa, ab; upk(a, aa, ab);
        a = pk(fmaxf(aa, 0.f), fmaxf(ab, 0.f));
        const f2* w2 = cw.W2T[l][j];
#pragma unroll
        for (int d = 0; d < DM; d++) acc[d] = fma2(a, w2[d], acc[d]);
    }
#pragma unroll
    for (int d = 0; d < DM; d++) h[d] = add2(h[d], acc[d]);
}

// ---------------- main kernel -----------------------------------------------
__global__ void __launch_bounds__(CTA_THREADS, 3)
tt_kernel(const float* __restrict__ gx, float* __restrict__ gout)
{
    __shared__ __align__(16) f2 skv[WPC][2][DM][SEQ_T];
    __shared__ f2 sx[WPC][SEQ_T];

    const int tid = threadIdx.x, warp = tid >> 5, lane = tid & 31;
    const int n0 = 2 * (blockIdx.x * WPC + warp);
    const int t = (lane < SEQ_T) ? lane : (SEQ_T - 1);
    const bool active = (lane < SEQ_T);

    f2* KK = &skv[warp][0][0][0];
    f2* VV = &skv[warp][1][0][0];

    // ---- input proj + layer-1 collapsed attention ----
    f2 h[DM];
    {
        float2 xv = *reinterpret_cast<const float2*>(gx + (size_t)t * NSEQ + n0);
        f2 xp = pk(xv.x, xv.y);
        if (active) sx[warp][t] = xp;
#pragma unroll
        for (int d = 0; d < DM; d++) h[d] = fma2(xp, cw.Win[d], cw.bin_[d]);
        __syncwarp();

        f2 c1[NH], c0[NH], S1[NH], Sx[NH];
#pragma unroll
        for (int hh = 0; hh < NH; hh++) {
            c1[hh] = fma2(cw.A1[hh], xp, cw.G1[hh]);   // (a*x_t + g)
            c0[hh] = fma2(cw.B1[hh], xp, cw.D1[hh]);   // (b*x_t + d)
            S1[hh] = 0ull; Sx[hh] = 0ull;
        }
#pragma unroll 4
        for (int s = 0; s < SEQ_T; s++) {
            f2 xs = sx[warp][s];
#pragma unroll
            for (int hh = 0; hh < NH; hh++) {
                f2 lg = fma2(c1[hh], xs, c0[hh]);
                float la, lb; upk(lg, la, lb);
                f2 p = pk(ex2(la), ex2(lb));
                S1[hh] = add2(S1[hh], p);
                Sx[hh] = fma2(p, xs, Sx[hh]);
            }
        }
        f2 Xb[NH];
#pragma unroll
        for (int hh = 0; hh < NH; hh++) {
            float sa, sb; upk(S1[hh], sa, sb);
            Xb[hh] = mul2(Sx[hh], pk(rcpf(sa), rcpf(sb)));
        }
#pragma unroll
        for (int d = 0; d < DM; d++) {
            f2 acc = fma2(Xb[0], cw.MoT[d][0], cw.co[d]);
            acc = fma2(Xb[1], cw.MoT[d][1], acc);
            acc = fma2(Xb[2], cw.MoT[d][2], acc);
            acc = fma2(Xb[3], cw.MoT[d][3], acc);
            h[d] = add2(h[d], acc);
        }
    }
    lnorm2(h, cw.ln1w[0], cw.ln1b[0]);
    ffn(h, 0);
    lnorm2(h, cw.ln2w[0], cw.ln2b[0]);

    // ---- layer 2 (full) ----
    __syncwarp();
#pragma unroll 4
    for (int j = 0; j < DM; j++) {
        f2 kkv = dot16c(h, cw.Wqkv2[DM + j], cw.bqkv2[DM + j]);
        if (active) KK[j * SEQ_T + t] = kkv;
    }
#pragma unroll 4
    for (int j = 0; j < DM; j++) {
        f2 vvv = dot16c(h, cw.Wqkv2[2*DM + j], cw.bqkv2[2*DM + j]);
        if (active) VV[j * SEQ_T + t] = vvv;
    }
    f2 q[DM];
    {
        const f2 qs = dupf(0.5f * 1.4426950408889634f);
#pragma unroll 4
        for (int j = 0; j < DM; j++)
            q[j] = mul2(dot16c(h, cw.Wqkv2[j], cw.bqkv2[j]), qs);
    }
    __syncwarp();

    f2 lsum[NH], ctx[DM];
#pragma unroll
    for (int hh = 0; hh < NH; hh++) lsum[hh] = 0ull;
#pragma unroll
    for (int d = 0; d < DM; d++) ctx[d] = 0ull;

#pragma unroll 2
    for (int s2 = 0; s2 < SEQ_T / 2; s2++) {
        const int s = 2 * s2;
#pragma unroll
        for (int hh = 0; hh < NH; hh++) {
            const int d0 = hh * HDIM;
            ulonglong2 k0 = *reinterpret_cast<const ulonglong2*>(&KK[(d0+0)*SEQ_T + s]);
            ulonglong2 k1 = *reinterpret_cast<const ulonglong2*>(&KK[(d0+1)*SEQ_T + s]);
            ulonglong2 k2 = *reinterpret_cast<const ulonglong2*>(&KK[(d0+2)*SEQ_T + s]);
            ulonglong2 k3 = *reinterpret_cast<const ulonglong2*>(&KK[(d0+3)*SEQ_T + s]);
            f2 la = mul2(q[d0+0], k0.x);
            f2 lb = mul2(q[d0+0], k0.y);
            la = fma2(q[d0+1], k1.x, la);
            lb = fma2(q[d0+1], k1.y, lb);
            la = fma2(q[d0+2], k2.x, la);
            lb = fma2(q[d0+2], k2.y, lb);
            la = fma2(q[d0+3], k3.x, la);
            lb = fma2(q[d0+3], k3.y, lb);
            float laA, laB, lbA, lbB;
            upk(la, laA, laB); upk(lb, lbA, lbB);
            f2 pa = pk(ex2(laA), ex2(laB));
            f2 pb = pk(ex2(lbA), ex2(lbB));
            lsum[hh] = add2(lsum[hh], add2(pa, pb));
            ulonglong2 v0 = *reinterpret_cast<const ulonglong2*>(&VV[(d0+0)*SEQ_T + s]);
            ulonglong2 v1 = *reinterpret_cast<const ulonglong2*>(&VV[(d0+1)*SEQ_T + s]);
            ulonglong2 v2 = *reinterpret_cast<const ulonglong2*>(&VV[(d0+2)*SEQ_T + s]);
            ulonglong2 v3 = *reinterpret_cast<const ulonglong2*>(&VV[(d0+3)*SEQ_T + s]);
            ctx[d0+0] = fma2(pa, v0.x, ctx[d0+0]);
            ctx[d0+1] = fma2(pa, v1.x, ctx[d0+1]);
            ctx[d0+2] = fma2(pa, v2.x, ctx[d0+2]);
            ctx[d0+3] = fma2(pa, v3.x, ctx[d0+3]);
            ctx[d0+0] = fma2(pb, v0.y, ctx[d0+0]);
            ctx[d0+1] = fma2(pb, v1.y, ctx[d0+1]);
            ctx[d0+2] = fma2(pb, v2.y, ctx[d0+2]);
            ctx[d0+3] = fma2(pb, v3.y, ctx[d0+3]);
        }
    }
#pragma unroll
    for (int hh = 0; hh < NH; hh++) {
        float sa, sb; upk(lsum[hh], sa, sb);
        f2 inv = pk(rcpf(sa), rcpf(sb));
#pragma unroll
        for (int e = 0; e < HDIM; e++)
            ctx[hh*HDIM + e] = mul2(ctx[hh*HDIM + e], inv);
    }

#pragma unroll 4
    for (int d = 0; d < DM; d++)
        h[d] = add2(h[d], dot16c(ctx, cw.Wo2[d], cw.bo2[d]));
    lnorm2(h, cw.ln1w[1], cw.ln1b[1]);
    ffn(h, 1);
    lnorm2(h, cw.ln2w[1], cw.ln2b[1]);

    // ---- output ----
    f2 y2 = dot16c(h, cw.Wout, cw.bout_);
    if (active) {
        float ya, yb; upk(y2, ya, yb);
        *reinterpret_cast<float2*>(gout + (size_t)t * NSEQ + n0) = make_float2(ya, yb);
    }
}

extern "C" void kernel_launch(void* const* d_in, const int* in_sizes, int n_in,
                              void* d_out, int out_size)
{
    (void)in_sizes; (void)n_in; (void)out_size;
    const float* gx    = (const float*)d_in[0];
    const float* gWin  = (const float*)d_in[1];
    const float* gbin  = (const float*)d_in[2];
    const float* gWqkv = (const float*)d_in[3];
    const float* gbqkv = (const float*)d_in[4];
    const float* gWo   = (const float*)d_in[5];
    const float* gbo   = (const float*)d_in[6];
    const float* gln1w = (const float*)d_in[7];
    const float* gln1b = (const float*)d_in[8];
    const float* gW1   = (const float*)d_in[9];
    const float* gb1   = (const float*)d_in[10];
    const float* gW2   = (const float*)d_in[11];
    const float* gb2   = (const float*)d_in[12];
    const float* gln2w = (const float*)d_in[13];
    const float* gln2b = (const float*)d_in[14];
    const float* gWout = (const float*)d_in[15];
    const float* gbout = (const float*)d_in[16];
    float* gout = (float*)d_out;

    prep_kernel<<<8, 256>>>(gWqkv, gbqkv, gWo, gbo, gW1, gb1, gW2, gb2,
                            gln1w, gln1b, gln2w, gln2b, gWin, gbin, gWout, gbout);
    void* sp = nullptr;
    cudaGetSymbolAddress(&sp, g_stage);
    cudaMemcpyToSymbolAsync(cw, sp, sizeof(CW), 0, cudaMemcpyDeviceToDevice, 0);

    tt_kernel<<<(NSEQ/2) / WPC, CTA_THREADS>>>(gx, gout);
}